// round 8
// baseline (speedup 1.0000x reference)
#include <cuda_runtime.h>

#define Nn 8192
#define Dd 16
#define Cc 8
#define Rr 64
#define NROWS (Cc + Dd * (Cc + 1))   // 152

// ---------------------------------------------------------------------------
// Kernel A: new_emb[n,r] = sum_d alpha[n,d]*msg[n,d,r] + curr_emb[n,0,r]
// ---------------------------------------------------------------------------
__global__ __launch_bounds__(256) void new_emb_kernel(
    const float* __restrict__ msg,
    const float* __restrict__ alpha,
    const float* __restrict__ curr_emb,
    float* __restrict__ out_emb)
{
    const int idx = blockIdx.x * 256 + threadIdx.x;   // 0 .. N*R-1
    const int n = idx >> 6;
    const int r = idx & 63;

    const float* m = msg + (size_t)n * Dd * Rr + r;
    const float* a = alpha + (size_t)n * Dd;

    float acc = 0.f;
    #pragma unroll
    for (int d = 0; d < Dd; d++) acc += a[d] * m[d * Rr];
    acc += curr_emb[(size_t)n * Dd * Rr + r];
    out_emb[idx] = acc;
}

// ---------------------------------------------------------------------------
// fused score + topk + gather: one block per sample n
// ---------------------------------------------------------------------------
__device__ __forceinline__ float score_part(
    float4 a0, float4 a1, float4 s0, float4 s1, float4 ne0, float4 ne1)
{
    // fp32 term order identical to prior rounds: (a + s) - ne
    float d0 = (a0.x + s0.x) - ne0.x;
    float d1 = (a0.y + s0.y) - ne0.y;
    float d2 = (a0.z + s0.z) - ne0.z;
    float d3 = (a0.w + s0.w) - ne0.w;
    float d4 = (a1.x + s1.x) - ne1.x;
    float d5 = (a1.y + s1.y) - ne1.y;
    float d6 = (a1.z + s1.z) - ne1.z;
    float d7 = (a1.w + s1.w) - ne1.w;
    float q0 = fmaf(d0, d0, d1 * d1);
    float q1 = fmaf(d2, d2, d3 * d3);
    float q2 = fmaf(d4, d4, d5 * d5);
    float q3 = fmaf(d6, d6, d7 * d7);
    return (q0 + q1) + (q2 + q3);
}

__global__ __launch_bounds__(256, 3) void fused_kernel(
    const float* __restrict__ curr_node_mem,
    const float* __restrict__ curr_rel_mem,
    const float* __restrict__ nei_node_mem,
    const float* __restrict__ nei_rel_mem,
    const float* __restrict__ head_rel_emb,
    const float* __restrict__ head_emb,
    const float* __restrict__ new_emb,     // from kernel A (= out_emb)
    float* __restrict__ out_node,
    float* __restrict__ out_rel)
{
    const int n    = blockIdx.x;
    const int t    = threadIdx.x;
    const int w    = t >> 5;
    const int lane = t & 31;
    const int sub  = lane >> 3;
    const int sl   = lane & 7;

    __shared__ __align__(16) float  s_hr[Dd * Rr];   // head_rel_emb[n]
    __shared__ __align__(16) float  s_ne[Rr];        // new_emb[n]
    __shared__ double s_score[NROWS];
    __shared__ int    s_sel[Cc];

    const size_t baseDR  = (size_t)n * Dd * Rr;
    const size_t baseDCR = (size_t)n * Dd * Cc * Rr;

    // preload head_rel (1024 floats) and new_emb (64 floats) into smem
    ((float4*)s_hr)[t] = ((const float4*)(head_rel_emb + baseDR))[t];
    if (t < 16) ((float4*)s_ne)[t] = ((const float4*)(new_emb + (size_t)n * Rr))[t];
    __syncthreads();

    const float4 ne0 = ((const float4*)s_ne)[sl];
    const float4 ne1 = ((const float4*)s_ne)[8 + sl];

    // ---- phase 1: per-lane fp32 partials for all 5 row-iterations, loads
    //      batched before any shuffle (up to 20 LDG.128 in flight) ----
    float part[5];
    #pragma unroll
    for (int i = 0; i < 5; i++) {
        const int  j     = i * 32 + w * 4 + sub;
        const bool valid = (j < NROWS);
        part[i] = 0.f;
        if (valid) {
            const float4* pa;
            const float4* pb = nullptr;
            const float4* ph = nullptr;
            if (j < Cc) {
                pa = (const float4*)(curr_node_mem + baseDCR + (size_t)j * Rr);
                pb = (const float4*)(curr_rel_mem  + baseDCR + (size_t)j * Rr);
            } else {
                const int j2 = j - Cc;
                const int d  = j2 / 9;
                const int cc = j2 - d * 9;
                ph = (const float4*)(s_hr + d * Rr);
                if (cc < Cc) {
                    pa = (const float4*)(nei_node_mem + baseDCR + (size_t)(d * Cc + cc) * Rr);
                    pb = (const float4*)(nei_rel_mem  + baseDCR + (size_t)(d * Cc + cc) * Rr);
                } else {
                    pa = (const float4*)(head_emb + baseDR + (size_t)d * Rr);
                }
            }
            const float4 a0 = pa[sl];
            const float4 a1 = pa[8 + sl];
            float4 b0 = make_float4(0.f, 0.f, 0.f, 0.f);
            float4 b1 = make_float4(0.f, 0.f, 0.f, 0.f);
            if (pb) { b0 = pb[sl]; b1 = pb[8 + sl]; }
            float4 h0 = make_float4(0.f, 0.f, 0.f, 0.f);
            float4 h1 = make_float4(0.f, 0.f, 0.f, 0.f);
            if (ph) { h0 = ph[sl]; h1 = ph[8 + sl]; }

            float4 s0 = make_float4(b0.x + h0.x, b0.y + h0.y, b0.z + h0.z, b0.w + h0.w);
            float4 s1 = make_float4(b1.x + h1.x, b1.y + h1.y, b1.z + h1.z, b1.w + h1.w);

            part[i] = score_part(a0, a1, s0, s1, ne0, ne1);
        }
    }

    // ---- phase 2: fp64 8-lane combines + score stores ----
    #pragma unroll
    for (int i = 0; i < 5; i++) {
        const int  j     = i * 32 + w * 4 + sub;
        double s = (double)part[i];
        s += __shfl_down_sync(0xffffffffu, s, 4);
        s += __shfl_down_sync(0xffffffffu, s, 2);
        s += __shfl_down_sync(0xffffffffu, s, 1);
        if (j < NROWS && sl == 0) s_score[j] = s;
    }
    __syncthreads();

    // ---- phase 3: top-8 stable selection (max score, tie -> lower index) ----
    if (w == 0) {
        for (int k = 0; k < Cc; k++) {
            double bs = -1.0;
            int    bj = NROWS;
            for (int j = lane; j < NROWS; j += 32) {
                double s = s_score[j];
                if (s > bs || (s == bs && j < bj)) { bs = s; bj = j; }
            }
            #pragma unroll
            for (int off = 16; off; off >>= 1) {
                double os = __shfl_down_sync(0xffffffffu, bs, off);
                int    oj = __shfl_down_sync(0xffffffffu, bj, off);
                if (os > bs || (os == bs && oj < bj)) { bs = os; bj = oj; }
            }
            bj = __shfl_sync(0xffffffffu, bj, 0);
            if (lane == 0) { s_sel[k] = bj; s_score[bj] = -2.0; }
            __syncwarp();
        }
    }
    __syncthreads();

    // ---- phase 4: gather. warp w writes output row (n, w) ----
    // reference: f = n*C + topkind; nn = f/152, col = f%152 (cross-sample)
    {
        const int jsel = s_sel[w];
        const int f    = n * Cc + jsel;
        const int nn   = f / NROWS;
        const int col  = f - nn * NROWS;
        const size_t gDR  = (size_t)nn * Dd * Rr;
        const size_t gDCR = (size_t)nn * Dd * Cc * Rr;

        float2 a, b;
        if (col < Cc) {
            a = ((const float2*)(curr_node_mem + gDCR + (size_t)col * Rr))[lane];
            b = ((const float2*)(curr_rel_mem  + gDCR + (size_t)col * Rr))[lane];
        } else {
            int c2 = col - Cc;
            int d  = c2 / 9;
            int cc = c2 - d * 9;
            float2 h = ((const float2*)(head_rel_emb + gDR + (size_t)d * Rr))[lane];
            if (cc < Cc) {
                a = ((const float2*)(nei_node_mem + gDCR + (size_t)(d * Cc + cc) * Rr))[lane];
                float2 bb = ((const float2*)(nei_rel_mem + gDCR + (size_t)(d * Cc + cc) * Rr))[lane];
                b.x = bb.x + h.x;  b.y = bb.y + h.y;
            } else {
                a = ((const float2*)(head_emb + gDR + (size_t)d * Rr))[lane];
                b = h;
            }
        }
        ((float2*)(out_node + ((size_t)n * Cc + w) * Rr))[lane] = a;
        ((float2*)(out_rel  + ((size_t)n * Cc + w) * Rr))[lane] = b;
    }
}

// ---------------------------------------------------------------------------
extern "C" void kernel_launch(void* const* d_in, const int* in_sizes, int n_in,
                              void* d_out, int out_size)
{
    (void)in_sizes; (void)n_in; (void)out_size;
    const float* curr_emb      = (const float*)d_in[0];
    const float* alpha         = (const float*)d_in[1];
    const float* msg           = (const float*)d_in[2];
    const float* curr_node_mem = (const float*)d_in[3];
    const float* curr_rel_mem  = (const float*)d_in[4];
    const float* nei_node_mem  = (const float*)d_in[5];
    const float* nei_rel_mem   = (const float*)d_in[6];
    const float* head_rel_emb  = (const float*)d_in[7];
    const float* head_emb      = (const float*)d_in[8];

    float* out_emb  = (float*)d_out;                     // N*R
    float* out_node = out_emb  + (size_t)Nn * Rr;        // N*C*R
    float* out_rel  = out_node + (size_t)Nn * Cc * Rr;   // N*C*R

    // A: new_emb
    new_emb_kernel<<<(Nn * Rr) / 256, 256>>>(msg, alpha, curr_emb, out_emb);

    // fused: score + topk + gather, block per sample
    fused_kernel<<<Nn, 256>>>(curr_node_mem, curr_rel_mem,
                              nei_node_mem, nei_rel_mem,
                              head_rel_emb, head_emb, out_emb,
                              out_node, out_rel);
}

// round 9
// speedup vs baseline: 1.4849x; 1.4849x over previous
#include <cuda_runtime.h>

#define Nn 8192
#define Dd 16
#define Cc 8
#define Rr 64
#define NROWS (Cc + Dd * (Cc + 1))   // 152

// fp64 score scratch: 8192*152*8B = ~10 MB (static device global, allowed)
__device__ double g_scores[(size_t)Nn * NROWS];

// ---------------------------------------------------------------------------
// Kernel A: new_emb[n,r] = sum_d alpha[n,d]*msg[n,d,r] + curr_emb[n,0,r]
// ---------------------------------------------------------------------------
__global__ __launch_bounds__(256) void new_emb_kernel(
    const float* __restrict__ msg,
    const float* __restrict__ alpha,
    const float* __restrict__ curr_emb,
    float* __restrict__ out_emb)
{
    const int idx = blockIdx.x * 256 + threadIdx.x;   // 0 .. N*R-1
    const int n = idx >> 6;
    const int r = idx & 63;

    const float* m = msg + (size_t)n * Dd * Rr + r;
    const float* a = alpha + (size_t)n * Dd;

    float acc = 0.f;
    #pragma unroll
    for (int d = 0; d < Dd; d++) acc += a[d] * m[d * Rr];
    acc += curr_emb[(size_t)n * Dd * Rr + r];
    out_emb[idx] = acc;
}

// ---------------------------------------------------------------------------
// per-row score math (identical fp32 order to prior rounds)
// ---------------------------------------------------------------------------
__device__ __forceinline__ float score_part(
    float4 a0, float4 a1, float4 s0, float4 s1, float4 ne0, float4 ne1)
{
    float d0 = (a0.x + s0.x) - ne0.x;
    float d1 = (a0.y + s0.y) - ne0.y;
    float d2 = (a0.z + s0.z) - ne0.z;
    float d3 = (a0.w + s0.w) - ne0.w;
    float d4 = (a1.x + s1.x) - ne1.x;
    float d5 = (a1.y + s1.y) - ne1.y;
    float d6 = (a1.z + s1.z) - ne1.z;
    float d7 = (a1.w + s1.w) - ne1.w;
    float q0 = fmaf(d0, d0, d1 * d1);
    float q1 = fmaf(d2, d2, d3 * d3);
    float q2 = fmaf(d4, d4, d5 * d5);
    float q3 = fmaf(d6, d6, d7 * d7);
    return (q0 + q1) + (q2 + q3);
}

// ---------------------------------------------------------------------------
// Kernel B: score every row (n,j). Warp = 8 rows (two quads j, j+4),
// 8-lane group per row, 2x float4 per lane per operand. fp32 per-lane tree,
// exact fp64 8-lane combine. No __ldcs. 152 % 8 == 0 -> warp never spans n.
// ---------------------------------------------------------------------------
__global__ __launch_bounds__(256, 3) void score_kernel(
    const float* __restrict__ curr_node_mem,
    const float* __restrict__ curr_rel_mem,
    const float* __restrict__ nei_node_mem,
    const float* __restrict__ nei_rel_mem,
    const float* __restrict__ head_rel_emb,
    const float* __restrict__ head_emb,
    const float* __restrict__ new_emb)
{
    const int gw   = (blockIdx.x * 256 + threadIdx.x) >> 5;
    const int lane = threadIdx.x & 31;
    const int sub  = lane >> 3;
    const int sl   = lane & 7;

    const int rbase = gw * 8;                 // 8 consecutive rows per warp
    const int n     = rbase / NROWS;
    const int jb    = rbase - n * NROWS;      // first row index within n

    const size_t baseDR  = (size_t)n * Dd * Rr;
    const size_t baseDCR = (size_t)n * Dd * Cc * Rr;

    const float4* pn = (const float4*)(new_emb + (size_t)n * Rr);
    const float4 ne0 = pn[sl];
    const float4 ne1 = pn[8 + sl];

    double res[2];

    #pragma unroll
    for (int k = 0; k < 2; k++) {
        const int j = jb + k * 4 + sub;

        const float4* pa;
        const float4* pb = nullptr;
        const float4* ph = nullptr;
        if (j < Cc) {
            pa = (const float4*)(curr_node_mem + baseDCR + (size_t)j * Rr);
            pb = (const float4*)(curr_rel_mem  + baseDCR + (size_t)j * Rr);
        } else {
            const int j2 = j - Cc;
            const int d  = j2 / 9;
            const int cc = j2 - d * 9;
            ph = (const float4*)(head_rel_emb + baseDR + (size_t)d * Rr);
            if (cc < Cc) {
                pa = (const float4*)(nei_node_mem + baseDCR + (size_t)(d * Cc + cc) * Rr);
                pb = (const float4*)(nei_rel_mem  + baseDCR + (size_t)(d * Cc + cc) * Rr);
            } else {
                pa = (const float4*)(head_emb + baseDR + (size_t)d * Rr);
            }
        }

        const float4 a0 = pa[sl];
        const float4 a1 = pa[8 + sl];
        float4 b0 = make_float4(0.f, 0.f, 0.f, 0.f);
        float4 b1 = make_float4(0.f, 0.f, 0.f, 0.f);
        if (pb) { b0 = pb[sl]; b1 = pb[8 + sl]; }
        float4 h0 = make_float4(0.f, 0.f, 0.f, 0.f);
        float4 h1 = make_float4(0.f, 0.f, 0.f, 0.f);
        if (ph) { h0 = ph[sl]; h1 = ph[8 + sl]; }

        float4 s0 = make_float4(b0.x + h0.x, b0.y + h0.y, b0.z + h0.z, b0.w + h0.w);
        float4 s1 = make_float4(b1.x + h1.x, b1.y + h1.y, b1.z + h1.z, b1.w + h1.w);

        double s = (double)score_part(a0, a1, s0, s1, ne0, ne1);
        s += __shfl_down_sync(0xffffffffu, s, 4);
        s += __shfl_down_sync(0xffffffffu, s, 2);
        s += __shfl_down_sync(0xffffffffu, s, 1);
        res[k] = s;
    }

    if (sl == 0) {
        g_scores[(size_t)rbase + sub]     = res[0];
        g_scores[(size_t)rbase + 4 + sub] = res[1];
    }
}

// ---------------------------------------------------------------------------
// Kernel C: per-n topk (stable) + gather. Block per n, 256 threads.
// ---------------------------------------------------------------------------
__global__ __launch_bounds__(256) void topk_gather_kernel(
    const float* __restrict__ curr_node_mem,
    const float* __restrict__ curr_rel_mem,
    const float* __restrict__ nei_node_mem,
    const float* __restrict__ nei_rel_mem,
    const float* __restrict__ head_rel_emb,
    const float* __restrict__ head_emb,
    float* __restrict__ out_node,
    float* __restrict__ out_rel)
{
    const int n    = blockIdx.x;
    const int t    = threadIdx.x;
    const int w    = t >> 5;
    const int lane = t & 31;

    __shared__ double s_score[NROWS];
    __shared__ int    s_sel[Cc];

    if (t < NROWS) s_score[t] = g_scores[(size_t)n * NROWS + t];
    __syncthreads();

    if (w == 0) {
        for (int k = 0; k < Cc; k++) {
            double bs = -1.0;
            int    bj = NROWS;
            for (int j = lane; j < NROWS; j += 32) {
                double s = s_score[j];
                if (s > bs || (s == bs && j < bj)) { bs = s; bj = j; }
            }
            #pragma unroll
            for (int off = 16; off; off >>= 1) {
                double os = __shfl_down_sync(0xffffffffu, bs, off);
                int    oj = __shfl_down_sync(0xffffffffu, bj, off);
                if (os > bs || (os == bs && oj < bj)) { bs = os; bj = oj; }
            }
            bj = __shfl_sync(0xffffffffu, bj, 0);
            if (lane == 0) { s_sel[k] = bj; s_score[bj] = -2.0; }
            __syncwarp();
        }
    }
    __syncthreads();

    // gather: warp w writes output row (n, w)
    // reference: f = n*C + topkind; nn = f/152, col = f%152 (cross-sample)
    const int jsel = s_sel[w];
    const int f    = n * Cc + jsel;
    const int nn   = f / NROWS;
    const int col  = f - nn * NROWS;
    const size_t gDR  = (size_t)nn * Dd * Rr;
    const size_t gDCR = (size_t)nn * Dd * Cc * Rr;

    float2 a, b;
    if (col < Cc) {
        a = ((const float2*)(curr_node_mem + gDCR + (size_t)col * Rr))[lane];
        b = ((const float2*)(curr_rel_mem  + gDCR + (size_t)col * Rr))[lane];
    } else {
        int c2 = col - Cc;
        int d  = c2 / 9;
        int cc = c2 - d * 9;
        float2 h = ((const float2*)(head_rel_emb + gDR + (size_t)d * Rr))[lane];
        if (cc < Cc) {
            a = ((const float2*)(nei_node_mem + gDCR + (size_t)(d * Cc + cc) * Rr))[lane];
            float2 bb = ((const float2*)(nei_rel_mem + gDCR + (size_t)(d * Cc + cc) * Rr))[lane];
            b.x = bb.x + h.x;  b.y = bb.y + h.y;
        } else {
            a = ((const float2*)(head_emb + gDR + (size_t)d * Rr))[lane];
            b = h;
        }
    }
    ((float2*)(out_node + ((size_t)n * Cc + w) * Rr))[lane] = a;
    ((float2*)(out_rel  + ((size_t)n * Cc + w) * Rr))[lane] = b;
}

// ---------------------------------------------------------------------------
extern "C" void kernel_launch(void* const* d_in, const int* in_sizes, int n_in,
                              void* d_out, int out_size)
{
    (void)in_sizes; (void)n_in; (void)out_size;
    const float* curr_emb      = (const float*)d_in[0];
    const float* alpha         = (const float*)d_in[1];
    const float* msg           = (const float*)d_in[2];
    const float* curr_node_mem = (const float*)d_in[3];
    const float* curr_rel_mem  = (const float*)d_in[4];
    const float* nei_node_mem  = (const float*)d_in[5];
    const float* nei_rel_mem   = (const float*)d_in[6];
    const float* head_rel_emb  = (const float*)d_in[7];
    const float* head_emb      = (const float*)d_in[8];

    float* out_emb  = (float*)d_out;                     // N*R
    float* out_node = out_emb  + (size_t)Nn * Rr;        // N*C*R
    float* out_rel  = out_node + (size_t)Nn * Cc * Rr;   // N*C*R

    // A: new_emb
    new_emb_kernel<<<(Nn * Rr) / 256, 256>>>(msg, alpha, curr_emb, out_emb);

    // B: scores (warp = 8 rows; exact cover: 8192*152/8 = 155648 warps)
    const int total_warps = (Nn * NROWS) / 8;            // 155648
    score_kernel<<<total_warps / 8, 256>>>(curr_node_mem, curr_rel_mem,
                                           nei_node_mem, nei_rel_mem,
                                           head_rel_emb, head_emb, out_emb);

    // C: topk + gather
    topk_gather_kernel<<<Nn, 256>>>(curr_node_mem, curr_rel_mem,
                                    nei_node_mem, nei_rel_mem,
                                    head_rel_emb, head_emb,
                                    out_node, out_rel);
}

// round 10
// speedup vs baseline: 2.2035x; 1.4839x over previous
#include <cuda_runtime.h>

#define Nn 8192
#define Dd 16
#define Cc 8
#define Rr 64
#define NROWS (Cc + Dd * (Cc + 1))   // 152

// fp32 score scratch: 8192*152*4B = ~5 MB (static device global, allowed)
__device__ float g_scores[(size_t)Nn * NROWS];

// ---------------------------------------------------------------------------
// Kernel A: new_emb[n,r] = sum_d alpha[n,d]*msg[n,d,r] + curr_emb[n,0,r]
// ---------------------------------------------------------------------------
__global__ __launch_bounds__(256) void new_emb_kernel(
    const float* __restrict__ msg,
    const float* __restrict__ alpha,
    const float* __restrict__ curr_emb,
    float* __restrict__ out_emb)
{
    const int idx = blockIdx.x * 256 + threadIdx.x;   // 0 .. N*R-1
    const int n = idx >> 6;
    const int r = idx & 63;

    const float* m = msg + (size_t)n * Dd * Rr + r;
    const float* a = alpha + (size_t)n * Dd;

    float acc = 0.f;
    #pragma unroll
    for (int d = 0; d < Dd; d++) acc += a[d] * m[d * Rr];
    acc += curr_emb[(size_t)n * Dd * Rr + r];
    out_emb[idx] = acc;
}

// ---------------------------------------------------------------------------
// Kernel B: score every row (n,j). Warp = 4 rows, 8-lane groups, 8 floats/lane
// (R4 champion layout). fp32 per-lane pairwise tree + fp32 3-step combine.
// ---------------------------------------------------------------------------
__global__ __launch_bounds__(256) void score_kernel(
    const float* __restrict__ curr_node_mem,
    const float* __restrict__ curr_rel_mem,
    const float* __restrict__ nei_node_mem,
    const float* __restrict__ nei_rel_mem,
    const float* __restrict__ head_rel_emb,
    const float* __restrict__ head_emb,
    const float* __restrict__ new_emb)
{
    const int gw   = (blockIdx.x * 256 + threadIdx.x) >> 5;
    const int lane = threadIdx.x & 31;
    const int sub  = lane >> 3;
    const int sl   = lane & 7;

    const int row = gw * 4 + sub;            // exact cover: 152 % 4 == 0
    const int n   = row / NROWS;
    const int j   = row - n * NROWS;

    const size_t baseDR  = (size_t)n * Dd * Rr;
    const size_t baseDCR = (size_t)n * Dd * Cc * Rr;

    const float4* pa;
    const float4* pb = nullptr;
    const float4* ph = nullptr;
    if (j < Cc) {
        pa = (const float4*)(curr_node_mem + baseDCR + (size_t)j * Rr);
        pb = (const float4*)(curr_rel_mem  + baseDCR + (size_t)j * Rr);
    } else {
        const int j2 = j - Cc;
        const int d  = j2 / 9;
        const int cc = j2 - d * 9;
        ph = (const float4*)(head_rel_emb + baseDR + (size_t)d * Rr);
        if (cc < Cc) {
            pa = (const float4*)(nei_node_mem + baseDCR + (size_t)(d * Cc + cc) * Rr);
            pb = (const float4*)(nei_rel_mem  + baseDCR + (size_t)(d * Cc + cc) * Rr);
        } else {
            pa = (const float4*)(head_emb + baseDR + (size_t)d * Rr);
        }
    }

    // R4 champion load pattern (interleaved float4 pairs per lane)
    const float4 ne0 = ((const float4*)(new_emb + (size_t)n * Rr))[sl * 2 + 0];
    const float4 ne1 = ((const float4*)(new_emb + (size_t)n * Rr))[sl * 2 + 1];
    const float4 a0  = pa[sl * 2 + 0];
    const float4 a1  = pa[sl * 2 + 1];
    float4 b0 = make_float4(0.f, 0.f, 0.f, 0.f);
    float4 b1 = make_float4(0.f, 0.f, 0.f, 0.f);
    if (pb) { b0 = pb[sl * 2 + 0]; b1 = pb[sl * 2 + 1]; }
    float4 h0 = make_float4(0.f, 0.f, 0.f, 0.f);
    float4 h1 = make_float4(0.f, 0.f, 0.f, 0.f);
    if (ph) { h0 = ph[sl * 2 + 0]; h1 = ph[sl * 2 + 1]; }

    // fp32 term order identical to prior rounds: (a + (b+h)) - ne
    float d0 = (a0.x + (b0.x + h0.x)) - ne0.x;
    float d1 = (a0.y + (b0.y + h0.y)) - ne0.y;
    float d2 = (a0.z + (b0.z + h0.z)) - ne0.z;
    float d3 = (a0.w + (b0.w + h0.w)) - ne0.w;
    float d4 = (a1.x + (b1.x + h1.x)) - ne1.x;
    float d5 = (a1.y + (b1.y + h1.y)) - ne1.y;
    float d6 = (a1.z + (b1.z + h1.z)) - ne1.z;
    float d7 = (a1.w + (b1.w + h1.w)) - ne1.w;

    // fp32 pairwise tree of squares
    float q0 = fmaf(d0, d0, d1 * d1);
    float q1 = fmaf(d2, d2, d3 * d3);
    float q2 = fmaf(d4, d4, d5 * d5);
    float q3 = fmaf(d6, d6, d7 * d7);
    float s  = (q0 + q1) + (q2 + q3);

    // fp32 3-step combine across the 8-lane group
    s += __shfl_down_sync(0xffffffffu, s, 4);
    s += __shfl_down_sync(0xffffffffu, s, 2);
    s += __shfl_down_sync(0xffffffffu, s, 1);
    if (sl == 0) g_scores[row] = s;
}

// ---------------------------------------------------------------------------
// Kernel C: per-n topk (stable) + gather. Block per n, 256 threads.
// ---------------------------------------------------------------------------
__global__ __launch_bounds__(256) void topk_gather_kernel(
    const float* __restrict__ curr_node_mem,
    const float* __restrict__ curr_rel_mem,
    const float* __restrict__ nei_node_mem,
    const float* __restrict__ nei_rel_mem,
    const float* __restrict__ head_rel_emb,
    const float* __restrict__ head_emb,
    float* __restrict__ out_node,
    float* __restrict__ out_rel)
{
    const int n    = blockIdx.x;
    const int t    = threadIdx.x;
    const int w    = t >> 5;
    const int lane = t & 31;

    __shared__ float s_score[NROWS];
    __shared__ int   s_sel[Cc];

    if (t < NROWS) s_score[t] = g_scores[(size_t)n * NROWS + t];
    __syncthreads();

    if (w == 0) {
        for (int k = 0; k < Cc; k++) {
            float bs = -1.0f;
            int   bj = NROWS;
            for (int j = lane; j < NROWS; j += 32) {
                float s = s_score[j];
                if (s > bs || (s == bs && j < bj)) { bs = s; bj = j; }
            }
            #pragma unroll
            for (int off = 16; off; off >>= 1) {
                float os = __shfl_down_sync(0xffffffffu, bs, off);
                int   oj = __shfl_down_sync(0xffffffffu, bj, off);
                if (os > bs || (os == bs && oj < bj)) { bs = os; bj = oj; }
            }
            bj = __shfl_sync(0xffffffffu, bj, 0);
            if (lane == 0) { s_sel[k] = bj; s_score[bj] = -2.0f; }
            __syncwarp();
        }
    }
    __syncthreads();

    // gather: warp w writes output row (n, w)
    // reference: f = n*C + topkind; nn = f/152, col = f%152 (cross-sample)
    const int jsel = s_sel[w];
    const int f    = n * Cc + jsel;
    const int nn   = f / NROWS;
    const int col  = f - nn * NROWS;
    const size_t gDR  = (size_t)nn * Dd * Rr;
    const size_t gDCR = (size_t)nn * Dd * Cc * Rr;

    float2 a, b;
    if (col < Cc) {
        a = ((const float2*)(curr_node_mem + gDCR + (size_t)col * Rr))[lane];
        b = ((const float2*)(curr_rel_mem  + gDCR + (size_t)col * Rr))[lane];
    } else {
        int c2 = col - Cc;
        int d  = c2 / 9;
        int cc = c2 - d * 9;
        float2 h = ((const float2*)(head_rel_emb + gDR + (size_t)d * Rr))[lane];
        if (cc < Cc) {
            a = ((const float2*)(nei_node_mem + gDCR + (size_t)(d * Cc + cc) * Rr))[lane];
            float2 bb = ((const float2*)(nei_rel_mem + gDCR + (size_t)(d * Cc + cc) * Rr))[lane];
            b.x = bb.x + h.x;  b.y = bb.y + h.y;
        } else {
            a = ((const float2*)(head_emb + gDR + (size_t)d * Rr))[lane];
            b = h;
        }
    }
    ((float2*)(out_node + ((size_t)n * Cc + w) * Rr))[lane] = a;
    ((float2*)(out_rel  + ((size_t)n * Cc + w) * Rr))[lane] = b;
}

// ---------------------------------------------------------------------------
extern "C" void kernel_launch(void* const* d_in, const int* in_sizes, int n_in,
                              void* d_out, int out_size)
{
    (void)in_sizes; (void)n_in; (void)out_size;
    const float* curr_emb      = (const float*)d_in[0];
    const float* alpha         = (const float*)d_in[1];
    const float* msg           = (const float*)d_in[2];
    const float* curr_node_mem = (const float*)d_in[3];
    const float* curr_rel_mem  = (const float*)d_in[4];
    const float* nei_node_mem  = (const float*)d_in[5];
    const float* nei_rel_mem   = (const float*)d_in[6];
    const float* head_rel_emb  = (const float*)d_in[7];
    const float* head_emb      = (const float*)d_in[8];

    float* out_emb  = (float*)d_out;                     // N*R
    float* out_node = out_emb  + (size_t)Nn * Rr;        // N*C*R
    float* out_rel  = out_node + (size_t)Nn * Cc * Rr;   // N*C*R

    // A: new_emb
    new_emb_kernel<<<(Nn * Rr) / 256, 256>>>(msg, alpha, curr_emb, out_emb);

    // B: scores (warp = 4 rows; exact cover)
    const int total_warps = (Nn * NROWS) / 4;            // 311296
    score_kernel<<<total_warps / 8, 256>>>(curr_node_mem, curr_rel_mem,
                                           nei_node_mem, nei_rel_mem,
                                           head_rel_emb, head_emb, out_emb);

    // C: topk + gather
    topk_gather_kernel<<<Nn, 256>>>(curr_node_mem, curr_rel_mem,
                                    nei_node_mem, nei_rel_mem,
                                    head_rel_emb, head_emb,
                                    out_node, out_rel);
}

// round 11
// speedup vs baseline: 2.2433x; 1.0181x over previous
#include <cuda_runtime.h>

#define Nn 8192
#define Dd 16
#define Cc 8
#define Rr 64
#define NROWS (Cc + Dd * (Cc + 1))   // 152

// fp32 score scratch: 8192*152*4B = ~5 MB (static device global, allowed)
__device__ float g_scores[(size_t)Nn * NROWS];

// ---------------------------------------------------------------------------
// Kernel A: new_emb[n,r] = sum_d alpha[n,d]*msg[n,d,r] + curr_emb[n,0,r]
// ---------------------------------------------------------------------------
__global__ __launch_bounds__(256) void new_emb_kernel(
    const float* __restrict__ msg,
    const float* __restrict__ alpha,
    const float* __restrict__ curr_emb,
    float* __restrict__ out_emb)
{
    const int idx = blockIdx.x * 256 + threadIdx.x;   // 0 .. N*R-1
    const int n = idx >> 6;
    const int r = idx & 63;

    const float* m = msg + (size_t)n * Dd * Rr + r;
    const float* a = alpha + (size_t)n * Dd;

    float acc = 0.f;
    #pragma unroll
    for (int d = 0; d < Dd; d++) acc += a[d] * m[d * Rr];
    acc += curr_emb[(size_t)n * Dd * Rr + r];
    out_emb[idx] = acc;
}

// ---------------------------------------------------------------------------
// Kernel B: score every row (n,j). Warp = 4 rows, 8-lane groups, 8 floats/lane.
// CONTIGUOUS lane layout: lane sl loads float4 [sl] and [8+sl] -> each warp
// LDG.128 covers exactly one 128B line per row (full sector utilization).
// fp32 per-lane pairwise tree + fp32 3-step combine.
// ---------------------------------------------------------------------------
__global__ __launch_bounds__(256) void score_kernel(
    const float* __restrict__ curr_node_mem,
    const float* __restrict__ curr_rel_mem,
    const float* __restrict__ nei_node_mem,
    const float* __restrict__ nei_rel_mem,
    const float* __restrict__ head_rel_emb,
    const float* __restrict__ head_emb,
    const float* __restrict__ new_emb)
{
    const int gw   = (blockIdx.x * 256 + threadIdx.x) >> 5;
    const int lane = threadIdx.x & 31;
    const int sub  = lane >> 3;
    const int sl   = lane & 7;

    const int row = gw * 4 + sub;            // exact cover: 152 % 4 == 0
    const int n   = row / NROWS;
    const int j   = row - n * NROWS;

    const size_t baseDR  = (size_t)n * Dd * Rr;
    const size_t baseDCR = (size_t)n * Dd * Cc * Rr;

    const float4* pa;
    const float4* pb = nullptr;
    const float4* ph = nullptr;
    if (j < Cc) {
        pa = (const float4*)(curr_node_mem + baseDCR + (size_t)j * Rr);
        pb = (const float4*)(curr_rel_mem  + baseDCR + (size_t)j * Rr);
    } else {
        const int j2 = j - Cc;
        const int d  = j2 / 9;
        const int cc = j2 - d * 9;
        ph = (const float4*)(head_rel_emb + baseDR + (size_t)d * Rr);
        if (cc < Cc) {
            pa = (const float4*)(nei_node_mem + baseDCR + (size_t)(d * Cc + cc) * Rr);
            pb = (const float4*)(nei_rel_mem  + baseDCR + (size_t)(d * Cc + cc) * Rr);
        } else {
            pa = (const float4*)(head_emb + baseDR + (size_t)d * Rr);
        }
    }

    const float4* pn = (const float4*)(new_emb + (size_t)n * Rr);
    const float4 ne0 = pn[sl];
    const float4 ne1 = pn[8 + sl];
    const float4 a0  = pa[sl];
    const float4 a1  = pa[8 + sl];
    float4 b0 = make_float4(0.f, 0.f, 0.f, 0.f);
    float4 b1 = make_float4(0.f, 0.f, 0.f, 0.f);
    if (pb) { b0 = pb[sl]; b1 = pb[8 + sl]; }
    float4 h0 = make_float4(0.f, 0.f, 0.f, 0.f);
    float4 h1 = make_float4(0.f, 0.f, 0.f, 0.f);
    if (ph) { h0 = ph[sl]; h1 = ph[8 + sl]; }

    // fp32 term order: (a + (b+h)) - ne
    float d0 = (a0.x + (b0.x + h0.x)) - ne0.x;
    float d1 = (a0.y + (b0.y + h0.y)) - ne0.y;
    float d2 = (a0.z + (b0.z + h0.z)) - ne0.z;
    float d3 = (a0.w + (b0.w + h0.w)) - ne0.w;
    float d4 = (a1.x + (b1.x + h1.x)) - ne1.x;
    float d5 = (a1.y + (b1.y + h1.y)) - ne1.y;
    float d6 = (a1.z + (b1.z + h1.z)) - ne1.z;
    float d7 = (a1.w + (b1.w + h1.w)) - ne1.w;

    // fp32 pairwise tree of squares
    float q0 = fmaf(d0, d0, d1 * d1);
    float q1 = fmaf(d2, d2, d3 * d3);
    float q2 = fmaf(d4, d4, d5 * d5);
    float q3 = fmaf(d6, d6, d7 * d7);
    float s  = (q0 + q1) + (q2 + q3);

    // fp32 3-step combine across the 8-lane group
    s += __shfl_down_sync(0xffffffffu, s, 4);
    s += __shfl_down_sync(0xffffffffu, s, 2);
    s += __shfl_down_sync(0xffffffffu, s, 1);
    if (sl == 0) g_scores[row] = s;
}

// ---------------------------------------------------------------------------
// Kernel C: per-n topk (stable) + gather. Block per n, 256 threads.
// ---------------------------------------------------------------------------
__global__ __launch_bounds__(256) void topk_gather_kernel(
    const float* __restrict__ curr_node_mem,
    const float* __restrict__ curr_rel_mem,
    const float* __restrict__ nei_node_mem,
    const float* __restrict__ nei_rel_mem,
    const float* __restrict__ head_rel_emb,
    const float* __restrict__ head_emb,
    float* __restrict__ out_node,
    float* __restrict__ out_rel)
{
    const int n    = blockIdx.x;
    const int t    = threadIdx.x;
    const int w    = t >> 5;
    const int lane = t & 31;

    __shared__ float s_score[NROWS];
    __shared__ int   s_sel[Cc];

    if (t < NROWS) s_score[t] = g_scores[(size_t)n * NROWS + t];
    __syncthreads();

    if (w == 0) {
        for (int k = 0; k < Cc; k++) {
            float bs = -1.0f;
            int   bj = NROWS;
            for (int j = lane; j < NROWS; j += 32) {
                float s = s_score[j];
                if (s > bs || (s == bs && j < bj)) { bs = s; bj = j; }
            }
            #pragma unroll
            for (int off = 16; off; off >>= 1) {
                float os = __shfl_down_sync(0xffffffffu, bs, off);
                int   oj = __shfl_down_sync(0xffffffffu, bj, off);
                if (os > bs || (os == bs && oj < bj)) { bs = os; bj = oj; }
            }
            bj = __shfl_sync(0xffffffffu, bj, 0);
            if (lane == 0) { s_sel[k] = bj; s_score[bj] = -2.0f; }
            __syncwarp();
        }
    }
    __syncthreads();

    // gather: warp w writes output row (n, w)
    // reference: f = n*C + topkind; nn = f/152, col = f%152 (cross-sample)
    const int jsel = s_sel[w];
    const int f    = n * Cc + jsel;
    const int nn   = f / NROWS;
    const int col  = f - nn * NROWS;
    const size_t gDR  = (size_t)nn * Dd * Rr;
    const size_t gDCR = (size_t)nn * Dd * Cc * Rr;

    float2 a, b;
    if (col < Cc) {
        a = ((const float2*)(curr_node_mem + gDCR + (size_t)col * Rr))[lane];
        b = ((const float2*)(curr_rel_mem  + gDCR + (size_t)col * Rr))[lane];
    } else {
        int c2 = col - Cc;
        int d  = c2 / 9;
        int cc = c2 - d * 9;
        float2 h = ((const float2*)(head_rel_emb + gDR + (size_t)d * Rr))[lane];
        if (cc < Cc) {
            a = ((const float2*)(nei_node_mem + gDCR + (size_t)(d * Cc + cc) * Rr))[lane];
            float2 bb = ((const float2*)(nei_rel_mem + gDCR + (size_t)(d * Cc + cc) * Rr))[lane];
            b.x = bb.x + h.x;  b.y = bb.y + h.y;
        } else {
            a = ((const float2*)(head_emb + gDR + (size_t)d * Rr))[lane];
            b = h;
        }
    }
    ((float2*)(out_node + ((size_t)n * Cc + w) * Rr))[lane] = a;
    ((float2*)(out_rel  + ((size_t)n * Cc + w) * Rr))[lane] = b;
}

// ---------------------------------------------------------------------------
extern "C" void kernel_launch(void* const* d_in, const int* in_sizes, int n_in,
                              void* d_out, int out_size)
{
    (void)in_sizes; (void)n_in; (void)out_size;
    const float* curr_emb      = (const float*)d_in[0];
    const float* alpha         = (const float*)d_in[1];
    const float* msg           = (const float*)d_in[2];
    const float* curr_node_mem = (const float*)d_in[3];
    const float* curr_rel_mem  = (const float*)d_in[4];
    const float* nei_node_mem  = (const float*)d_in[5];
    const float* nei_rel_mem   = (const float*)d_in[6];
    const float* head_rel_emb  = (const float*)d_in[7];
    const float* head_emb      = (const float*)d_in[8];

    float* out_emb  = (float*)d_out;                     // N*R
    float* out_node = out_emb  + (size_t)Nn * Rr;        // N*C*R
    float* out_rel  = out_node + (size_t)Nn * Cc * Rr;   // N*C*R

    // A: new_emb
    new_emb_kernel<<<(Nn * Rr) / 256, 256>>>(msg, alpha, curr_emb, out_emb);

    // B: scores (warp = 4 rows; exact cover)
    const int total_warps = (Nn * NROWS) / 4;            // 311296
    score_kernel<<<total_warps / 8, 256>>>(curr_node_mem, curr_rel_mem,
                                           nei_node_mem, nei_rel_mem,
                                           head_rel_emb, head_emb, out_emb);

    // C: topk + gather
    topk_gather_kernel<<<Nn, 256>>>(curr_node_mem, curr_rel_mem,
                                    nei_node_mem, nei_rel_mem,
                                    head_rel_emb, head_emb,
                                    out_node, out_rel);
}

// round 12
// speedup vs baseline: 2.5738x; 1.1473x over previous
#include <cuda_runtime.h>

#define Nn 8192
#define Dd 16
#define Cc 8
#define Rr 64
#define NROWS (Cc + Dd * (Cc + 1))   // 152

// fp32 score scratch: 8192*152*4B = ~5 MB (static device global, allowed)
__device__ float g_scores[(size_t)Nn * NROWS];

// ---------------------------------------------------------------------------
// Kernel A: new_emb[n,r] = sum_d alpha[n,d]*msg[n,d,r] + curr_emb[n,0,r]
// vectorized: one thread per (n, r-quad): 16x LDG.128 on msg
// ---------------------------------------------------------------------------
__global__ __launch_bounds__(256) void new_emb_kernel(
    const float* __restrict__ msg,
    const float* __restrict__ alpha,
    const float* __restrict__ curr_emb,
    float* __restrict__ out_emb)
{
    const int idx = blockIdx.x * 256 + threadIdx.x;   // 0 .. N*R/4-1
    const int n  = idx >> 4;                          // 16 quads per n
    const int q  = idx & 15;                          // r-quad index

    const float4* m4 = (const float4*)(msg + (size_t)n * Dd * Rr) + q;
    const float*  a  = alpha + (size_t)n * Dd;

    float4 acc = make_float4(0.f, 0.f, 0.f, 0.f);
    #pragma unroll
    for (int d = 0; d < Dd; d++) {
        const float4 mv = m4[d * (Rr / 4)];
        const float  ad = a[d];
        acc.x += ad * mv.x;
        acc.y += ad * mv.y;
        acc.z += ad * mv.z;
        acc.w += ad * mv.w;
    }
    const float4 ce = ((const float4*)(curr_emb + (size_t)n * Dd * Rr))[q];
    acc.x += ce.x;  acc.y += ce.y;  acc.z += ce.z;  acc.w += ce.w;
    ((float4*)out_emb)[idx] = acc;
}

// ---------------------------------------------------------------------------
// Kernel B (unchanged champion): warp = 4 rows, 8-lane groups, contiguous
// float4 loads, fp32 tree + fp32 3-step combine.
// ---------------------------------------------------------------------------
__global__ __launch_bounds__(256) void score_kernel(
    const float* __restrict__ curr_node_mem,
    const float* __restrict__ curr_rel_mem,
    const float* __restrict__ nei_node_mem,
    const float* __restrict__ nei_rel_mem,
    const float* __restrict__ head_rel_emb,
    const float* __restrict__ head_emb,
    const float* __restrict__ new_emb)
{
    const int gw   = (blockIdx.x * 256 + threadIdx.x) >> 5;
    const int lane = threadIdx.x & 31;
    const int sub  = lane >> 3;
    const int sl   = lane & 7;

    const int row = gw * 4 + sub;            // exact cover: 152 % 4 == 0
    const int n   = row / NROWS;
    const int j   = row - n * NROWS;

    const size_t baseDR  = (size_t)n * Dd * Rr;
    const size_t baseDCR = (size_t)n * Dd * Cc * Rr;

    const float4* pa;
    const float4* pb = nullptr;
    const float4* ph = nullptr;
    if (j < Cc) {
        pa = (const float4*)(curr_node_mem + baseDCR + (size_t)j * Rr);
        pb = (const float4*)(curr_rel_mem  + baseDCR + (size_t)j * Rr);
    } else {
        const int j2 = j - Cc;
        const int d  = j2 / 9;
        const int cc = j2 - d * 9;
        ph = (const float4*)(head_rel_emb + baseDR + (size_t)d * Rr);
        if (cc < Cc) {
            pa = (const float4*)(nei_node_mem + baseDCR + (size_t)(d * Cc + cc) * Rr);
            pb = (const float4*)(nei_rel_mem  + baseDCR + (size_t)(d * Cc + cc) * Rr);
        } else {
            pa = (const float4*)(head_emb + baseDR + (size_t)d * Rr);
        }
    }

    const float4* pn = (const float4*)(new_emb + (size_t)n * Rr);
    const float4 ne0 = pn[sl];
    const float4 ne1 = pn[8 + sl];
    const float4 a0  = pa[sl];
    const float4 a1  = pa[8 + sl];
    float4 b0 = make_float4(0.f, 0.f, 0.f, 0.f);
    float4 b1 = make_float4(0.f, 0.f, 0.f, 0.f);
    if (pb) { b0 = pb[sl]; b1 = pb[8 + sl]; }
    float4 h0 = make_float4(0.f, 0.f, 0.f, 0.f);
    float4 h1 = make_float4(0.f, 0.f, 0.f, 0.f);
    if (ph) { h0 = ph[sl]; h1 = ph[8 + sl]; }

    float d0 = (a0.x + (b0.x + h0.x)) - ne0.x;
    float d1 = (a0.y + (b0.y + h0.y)) - ne0.y;
    float d2 = (a0.z + (b0.z + h0.z)) - ne0.z;
    float d3 = (a0.w + (b0.w + h0.w)) - ne0.w;
    float d4 = (a1.x + (b1.x + h1.x)) - ne1.x;
    float d5 = (a1.y + (b1.y + h1.y)) - ne1.y;
    float d6 = (a1.z + (b1.z + h1.z)) - ne1.z;
    float d7 = (a1.w + (b1.w + h1.w)) - ne1.w;

    float q0 = fmaf(d0, d0, d1 * d1);
    float q1 = fmaf(d2, d2, d3 * d3);
    float q2 = fmaf(d4, d4, d5 * d5);
    float q3 = fmaf(d6, d6, d7 * d7);
    float s  = (q0 + q1) + (q2 + q3);

    s += __shfl_down_sync(0xffffffffu, s, 4);
    s += __shfl_down_sync(0xffffffffu, s, 2);
    s += __shfl_down_sync(0xffffffffu, s, 1);
    if (sl == 0) g_scores[row] = s;
}

// ---------------------------------------------------------------------------
// Kernel C: one WARP per n. No smem, no block syncs. 8 warps/block.
// ---------------------------------------------------------------------------
__global__ __launch_bounds__(256) void topk_gather_kernel(
    const float* __restrict__ curr_node_mem,
    const float* __restrict__ curr_rel_mem,
    const float* __restrict__ nei_node_mem,
    const float* __restrict__ nei_rel_mem,
    const float* __restrict__ head_rel_emb,
    const float* __restrict__ head_emb,
    float* __restrict__ out_node,
    float* __restrict__ out_rel)
{
    const int n    = blockIdx.x * 8 + (threadIdx.x >> 5);
    const int lane = threadIdx.x & 31;

    // load this n's 152 scores: lane holds j = lane + 32*i
    float v[5];
    #pragma unroll
    for (int i = 0; i < 5; i++) {
        const int j = lane + 32 * i;
        v[i] = (j < NROWS) ? g_scores[(size_t)n * NROWS + j] : -3.0f;
    }

    // 8x stable warp arg-max (max score, tie -> lower index)
    int sel[Cc];
    #pragma unroll
    for (int k = 0; k < Cc; k++) {
        float bs = -1.0f;
        int   bj = NROWS;
        #pragma unroll
        for (int i = 0; i < 5; i++) {
            const int j = lane + 32 * i;
            if (v[i] > bs || (v[i] == bs && j < bj)) { bs = v[i]; bj = j; }
        }
        #pragma unroll
        for (int off = 16; off; off >>= 1) {
            float os = __shfl_down_sync(0xffffffffu, bs, off);
            int   oj = __shfl_down_sync(0xffffffffu, bj, off);
            if (os > bs || (os == bs && oj < bj)) { bs = os; bj = oj; }
        }
        bj = __shfl_sync(0xffffffffu, bj, 0);
        sel[k] = bj;
        if ((bj & 31) == lane) v[bj >> 5] = -2.0f;   // remove winner
    }

    // gather: this warp writes its 8 output rows
    // reference: f = n*C + topkind; nn = f/152, col = f%152 (cross-sample)
    #pragma unroll
    for (int k = 0; k < Cc; k++) {
        const int f   = n * Cc + sel[k];
        const int nn  = f / NROWS;
        const int col = f - nn * NROWS;
        const size_t gDR  = (size_t)nn * Dd * Rr;
        const size_t gDCR = (size_t)nn * Dd * Cc * Rr;

        float2 a, b;
        if (col < Cc) {
            a = ((const float2*)(curr_node_mem + gDCR + (size_t)col * Rr))[lane];
            b = ((const float2*)(curr_rel_mem  + gDCR + (size_t)col * Rr))[lane];
        } else {
            int c2 = col - Cc;
            int d  = c2 / 9;
            int cc = c2 - d * 9;
            float2 h = ((const float2*)(head_rel_emb + gDR + (size_t)d * Rr))[lane];
            if (cc < Cc) {
                a = ((const float2*)(nei_node_mem + gDCR + (size_t)(d * Cc + cc) * Rr))[lane];
                float2 bb = ((const float2*)(nei_rel_mem + gDCR + (size_t)(d * Cc + cc) * Rr))[lane];
                b.x = bb.x + h.x;  b.y = bb.y + h.y;
            } else {
                a = ((const float2*)(head_emb + gDR + (size_t)d * Rr))[lane];
                b = h;
            }
        }
        ((float2*)(out_node + ((size_t)n * Cc + k) * Rr))[lane] = a;
        ((float2*)(out_rel  + ((size_t)n * Cc + k) * Rr))[lane] = b;
    }
}

// ---------------------------------------------------------------------------
extern "C" void kernel_launch(void* const* d_in, const int* in_sizes, int n_in,
                              void* d_out, int out_size)
{
    (void)in_sizes; (void)n_in; (void)out_size;
    const float* curr_emb      = (const float*)d_in[0];
    const float* alpha         = (const float*)d_in[1];
    const float* msg           = (const float*)d_in[2];
    const float* curr_node_mem = (const float*)d_in[3];
    const float* curr_rel_mem  = (const float*)d_in[4];
    const float* nei_node_mem  = (const float*)d_in[5];
    const float* nei_rel_mem   = (const float*)d_in[6];
    const float* head_rel_emb  = (const float*)d_in[7];
    const float* head_emb      = (const float*)d_in[8];

    float* out_emb  = (float*)d_out;                     // N*R
    float* out_node = out_emb  + (size_t)Nn * Rr;        // N*C*R
    float* out_rel  = out_node + (size_t)Nn * Cc * Rr;   // N*C*R

    // A: new_emb (vectorized: N*R/4 threads)
    new_emb_kernel<<<(Nn * Rr / 4) / 256, 256>>>(msg, alpha, curr_emb, out_emb);

    // B: scores (warp = 4 rows; exact cover)
    const int total_warps = (Nn * NROWS) / 4;            // 311296
    score_kernel<<<total_warps / 8, 256>>>(curr_node_mem, curr_rel_mem,
                                           nei_node_mem, nei_rel_mem,
                                           head_rel_emb, head_emb, out_emb);

    // C: topk + gather, one warp per n
    topk_gather_kernel<<<Nn / 8, 256>>>(curr_node_mem, curr_rel_mem,
                                        nei_node_mem, nei_rel_mem,
                                        head_rel_emb, head_emb,
                                        out_node, out_rel);
}